// round 16
// baseline (speedup 1.0000x reference)
#include <cuda_runtime.h>
#include <cuda_bf16.h>
#include <math.h>
#include <stdint.h>

// ---------------- problem constants ----------------
#define Tt   96
#define Bb   64
#define TB   6144
#define DM   1024
#define DG   512
#define HH   256
#define G4   1024

// ---------------- scratch ----------------
__device__ float g_xgf[TB * G4];      // transposed [t][col'][b], col' = n*4+gate
__device__ float g_xgb[TB * G4];
__device__ float g_alpha[4 * Bb];
__device__ float g_shift[4 * Bb];

__device__ __nv_bfloat16 g_Uhi[TB * DM],  g_Ulo[TB * DM];
__device__ __nv_bfloat16 g_Uah[TB * 128], g_Ual[TB * 128];
__device__ __nv_bfloat16 g_Uvh[TB * DG],  g_Uvl[TB * DG];
__device__ __nv_bfloat16 g_Xhi[TB * DG],  g_Xlo[TB * DG];
__device__ __nv_bfloat16 g_Yhi[TB * DG],  g_Ylo[TB * DG];
__device__ __nv_bfloat16 g_Wah[DG * 128], g_Wal[DG * 128];
__device__ __nv_bfloat16 g_Wvh[DG * DG],  g_Wvl[DG * DG];
__device__ __nv_bfloat16 g_Wlh[DG * DM],  g_Wll[DG * DM];
__device__ __nv_bfloat16 g_W0fh[G4 * DG], g_W0fl[G4 * DG];
__device__ __nv_bfloat16 g_W0bh[G4 * DG], g_W0bl[G4 * DG];
__device__ __nv_bfloat16 g_W1fh[G4 * DG], g_W1fl[G4 * DG];
__device__ __nv_bfloat16 g_W1bh[G4 * DG], g_W1bl[G4 * DG];

// ---------------- helpers ----------------
__device__ __forceinline__ uint32_t smem_u32(const void* p) {
    uint32_t a;
    asm("{ .reg .u64 t; cvta.to.shared.u64 t, %1; cvt.u32.u64 %0, t; }" : "=r"(a) : "l"(p));
    return a;
}
__device__ __forceinline__ float fast_ex2(float x) {
    float r; asm("ex2.approx.f32 %0, %1;" : "=f"(r) : "f"(x)); return r;
}
__device__ __forceinline__ float fast_rcp(float x) {
    float r; asm("rcp.approx.f32 %0, %1;" : "=f"(r) : "f"(x)); return r;
}
__device__ __forceinline__ float fast_sigmoid(float x) {
    return fast_rcp(1.f + fast_ex2(-1.4426950408889634f * x));
}
__device__ __forceinline__ float fast_tanh(float x) {
    return 1.f - 2.f * fast_rcp(1.f + fast_ex2(2.8853900817779268f * x));
}
#define CP16(dst, src) \
    asm volatile("cp.async.cg.shared.global [%0], [%1], 16;" :: "r"(dst), "l"(src))
#define CP_COMMIT() asm volatile("cp.async.commit_group;" ::: "memory")
#define CP_WAIT(n)  asm volatile("cp.async.wait_group %0;" :: "n"(n) : "memory")

#define MMA16816(d, a, b) \
    asm volatile("mma.sync.aligned.m16n8k16.row.col.f32.bf16.bf16.f32 " \
        "{%0,%1,%2,%3}, {%4,%5,%6,%7}, {%8,%9}, {%0,%1,%2,%3};" \
        : "+f"((d)[0]), "+f"((d)[1]), "+f"((d)[2]), "+f"((d)[3]) \
        : "r"((a)[0]), "r"((a)[1]), "r"((a)[2]), "r"((a)[3]), "r"((b)[0]), "r"((b)[1]))

#define LDMX4(r, a) \
    asm volatile("ldmatrix.sync.aligned.m8n8.x4.shared.b16 {%0,%1,%2,%3}, [%4];" \
        : "=r"((r)[0]), "=r"((r)[1]), "=r"((r)[2]), "=r"((r)[3]) : "r"(a))

// ---------------- LN2 statistics ----------------
__global__ void stats_kernel(const float* __restrict__ r1, const float* __restrict__ r2,
                             const float* __restrict__ r3, const float* __restrict__ r4)
{
    int i = blockIdx.x >> 6;
    int b = blockIdx.x & 63;
    const float* r = (i == 0) ? r1 : (i == 1) ? r2 : (i == 2) ? r3 : r4;
    float s = 0.f, q = 0.f;
    const float4* base = (const float4*)(r + (size_t)b * DM);
    for (int t = 0; t < Tt; t++) {
        float4 v = base[(size_t)t * (Bb * DM / 4) + threadIdx.x];
        s += v.x + v.y + v.z + v.w;
        q += v.x * v.x + v.y * v.y + v.z * v.z + v.w * v.w;
    }
    __shared__ float ss[256], sq[256];
    ss[threadIdx.x] = s; sq[threadIdx.x] = q;
    __syncthreads();
    for (int st = 128; st > 0; st >>= 1) {
        if (threadIdx.x < st) { ss[threadIdx.x] += ss[threadIdx.x + st]; sq[threadIdx.x] += sq[threadIdx.x + st]; }
        __syncthreads();
    }
    if (threadIdx.x == 0) {
        const float inv_n = 1.f / (float)(Tt * DM);
        float m   = ss[0] * inv_n;
        float var = sq[0] * inv_n - m * m;
        float a   = 0.25f * rsqrtf(var + 1e-5f);
        g_alpha[i * Bb + b] = a;
        g_shift[i * Bb + b] = a * m;
    }
}

// ---------------- fused U build + bf16 split ----------------
__global__ void build_u_split(const float* __restrict__ r1, const float* __restrict__ r2,
                              const float* __restrict__ r3, const float* __restrict__ r4)
{
    size_t idx = (size_t)blockIdx.x * blockDim.x + threadIdx.x;
    size_t e   = idx * 4;
    int b = (int)((e >> 10) & 63);
    float a1 = g_alpha[b], a2 = g_alpha[64 + b], a3 = g_alpha[128 + b], a4 = g_alpha[192 + b];
    float sh = g_shift[b] + g_shift[64 + b] + g_shift[128 + b] + g_shift[192 + b];
    float4 v1 = ((const float4*)r1)[idx];
    float4 v2 = ((const float4*)r2)[idx];
    float4 v3 = ((const float4*)r3)[idx];
    float4 v4 = ((const float4*)r4)[idx];
    float o[4];
    o[0] = a1 * v1.x + a2 * v2.x + a3 * v3.x + a4 * v4.x - sh;
    o[1] = a1 * v1.y + a2 * v2.y + a3 * v3.y + a4 * v4.y - sh;
    o[2] = a1 * v1.z + a2 * v2.z + a3 * v3.z + a4 * v4.z - sh;
    o[3] = a1 * v1.w + a2 * v2.w + a3 * v3.w + a4 * v4.w - sh;
    __nv_bfloat162 hi0, hi1, lo0, lo1;
    hi0.x = __float2bfloat16(o[0]); hi0.y = __float2bfloat16(o[1]);
    hi1.x = __float2bfloat16(o[2]); hi1.y = __float2bfloat16(o[3]);
    lo0.x = __float2bfloat16(o[0] - __bfloat162float(hi0.x));
    lo0.y = __float2bfloat16(o[1] - __bfloat162float(hi0.y));
    lo1.x = __float2bfloat16(o[2] - __bfloat162float(hi1.x));
    lo1.y = __float2bfloat16(o[3] - __bfloat162float(hi1.y));
    ((__nv_bfloat162*)g_Uhi)[idx * 2]     = hi0;
    ((__nv_bfloat162*)g_Uhi)[idx * 2 + 1] = hi1;
    ((__nv_bfloat162*)g_Ulo)[idx * 2]     = lo0;
    ((__nv_bfloat162*)g_Ulo)[idx * 2 + 1] = lo1;
}

// ---------------- batched fp32 -> bf16 hi/lo ----------------
struct CJobs {
    const float*   in[7];
    __nv_bfloat16* hi[7];
    __nv_bfloat16* lo[7];
    int K[7], Kpad[7], total[7];
};
__global__ void convert_batch(CJobs j)
{
    int job = blockIdx.y;
    int idx = blockIdx.x * 256 + threadIdx.x;
    if (idx >= j.total[job]) return;
    int K = j.K[job], Kp = j.Kpad[job];
    int r = idx / Kp, c = idx - r * Kp;
    float v = (c < K) ? j.in[job][(size_t)r * K + c] : 0.f;
    __nv_bfloat16 h = __float2bfloat16(v);
    j.hi[job][idx] = h;
    j.lo[job][idx] = __float2bfloat16(v - __bfloat162float(h));
}

// ---------------- bf16-split GEMM, 128x64 tile, 3-stage, ldmatrix frags ----------------
#define RSTRIDE 80
#define ATSZ    (128 * RSTRIDE)
#define BTSZ    (64 * RSTRIDE)
#define STG_SZ  (2 * ATSZ + 2 * BTSZ)
#define SM_TILES 256
#define GEMM_SMEM (SM_TILES + 3 * STG_SZ)

#define GEMM_PROLOG() \
    extern __shared__ char smem[]; \
    const uint32_t sb = smem_u32(smem); \
    const int tid  = threadIdx.x; \
    const int lane = tid & 31, wid = tid >> 5; \
    const int wm = wid >> 1, wn = wid & 1; \
    const int g = lane >> 2, tig = lane & 3; \
    const int aRow = (lane & 7) + ((lane >> 3) & 1) * 8; \
    const int aCol = ((lane >> 4) & 1) * 16; \
    const int bRow = (lane & 7) + ((lane >> 4) & 1) * 8; \
    const int bCol = ((lane >> 3) & 1) * 16; \
    const int n0 = blockIdx.x * 64, m0 = blockIdx.y * 128; \
    float acc[2][4][4]; \
    _Pragma("unroll") for (int i = 0; i < 2; i++) \
    _Pragma("unroll") for (int jj = 0; jj < 4; jj++) \
    _Pragma("unroll") for (int x = 0; x < 4; x++) acc[i][jj][x] = 0.f;

#define LOAD_STAGE(st, ch) do { \
    int kc = (ch) << 5; \
    uint32_t stg = sb + SM_TILES + (st) * STG_SZ; \
    { int r = (tid * 2) >> 2, q = (tid * 2) & 3; \
      size_t off = (size_t)(m0 + r) * K + kc + q * 8; \
      uint32_t d = stg + r * RSTRIDE + q * 16; \
      CP16(d, Ahi + off); CP16(d + ATSZ, Alo + off); } \
    { int r = (tid * 2 + 1) >> 2, q = (tid * 2 + 1) & 3; \
      size_t off = (size_t)(m0 + r) * K + kc + q * 8; \
      uint32_t d = stg + r * RSTRIDE + q * 16; \
      CP16(d, Ahi + off); CP16(d + ATSZ, Alo + off); } \
    { int r = tid >> 2, q = tid & 3; \
      size_t off = (size_t)(n0 + r) * K + kc + q * 8; \
      uint32_t d = stg + 2 * ATSZ + r * RSTRIDE + q * 16; \
      CP16(d, Bhi + off); CP16(d + BTSZ, Blo + off); } \
    CP_COMMIT(); \
} while (0)

#define COMPUTE_STAGE(st) do { \
    uint32_t stg = sb + SM_TILES + (st) * STG_SZ; \
    uint32_t sAh = stg, sAl = stg + ATSZ, sBh = stg + 2 * ATSZ, sBl = stg + 2 * ATSZ + BTSZ; \
    _Pragma("unroll") \
    for (int kh = 0; kh < 2; kh++) { \
        uint32_t ah[2][4], al[2][4], bhv[2][4], blv[2][4]; \
        _Pragma("unroll") \
        for (int mt = 0; mt < 2; mt++) { \
            uint32_t ra = (uint32_t)(wm * 32 + mt * 16 + aRow) * RSTRIDE + kh * 32 + aCol; \
            LDMX4(ah[mt], sAh + ra); \
            LDMX4(al[mt], sAl + ra); \
        } \
        _Pragma("unroll") \
        for (int np = 0; np < 2; np++) { \
            uint32_t rb = (uint32_t)(wn * 32 + np * 16 + bRow) * RSTRIDE + kh * 32 + bCol; \
            LDMX4(bhv[np], sBh + rb); \
            LDMX4(blv[np], sBl + rb); \
        } \
        _Pragma("unroll") \
        for (int mt = 0; mt < 2; mt++) \
        _Pragma("unroll") \
            for (int nt = 0; nt < 4; nt++) MMA16816(acc[mt][nt], ah[mt], &bhv[nt >> 1][(nt & 1) * 2]); \
        _Pragma("unroll") \
        for (int mt = 0; mt < 2; mt++) \
        _Pragma("unroll") \
            for (int nt = 0; nt < 4; nt++) MMA16816(acc[mt][nt], ah[mt], &blv[nt >> 1][(nt & 1) * 2]); \
        _Pragma("unroll") \
        for (int mt = 0; mt < 2; mt++) \
        _Pragma("unroll") \
            for (int nt = 0; nt < 4; nt++) MMA16816(acc[mt][nt], al[mt], &bhv[nt >> 1][(nt & 1) * 2]); \
    } \
} while (0)

#define GEMM_MAINLOOP() \
    const int nch = K >> 5; \
    LOAD_STAGE(0, 0); \
    LOAD_STAGE(1, 1); \
    for (int ch = 0; ch < nch; ch++) { \
        const int st = ch % 3; \
        if (ch + 2 < nch) { CP_WAIT(1); } else { CP_WAIT(0); } \
        __syncthreads(); \
        if (ch + 2 < nch) LOAD_STAGE((ch + 2) % 3, ch + 2); \
        COMPUTE_STAGE(st); \
        __syncthreads(); \
    }

template <int OUTMODE>
__global__ void __launch_bounds__(256, 2) gemm_mma(
    const __nv_bfloat16* __restrict__ Ahi, const __nv_bfloat16* __restrict__ Alo,
    const __nv_bfloat16* __restrict__ Bhi, const __nv_bfloat16* __restrict__ Blo,
    const float* __restrict__ bias1,
    float* __restrict__ C, __nv_bfloat16* __restrict__ Chi, __nv_bfloat16* __restrict__ Clo,
    int K, int ldc, int coloff)
{
    GEMM_PROLOG();
    __shared__ float sBias[64];
    if (tid < 64) sBias[tid] = bias1[n0 + tid];
    GEMM_MAINLOOP();

#pragma unroll
    for (int mt = 0; mt < 2; mt++) {
        const int r0 = m0 + wm * 32 + mt * 16 + g;
        const int r1 = r0 + 8;
#pragma unroll
        for (int nt = 0; nt < 4; nt++) {
            const int cb = wn * 32 + nt * 8 + 2 * tig;
            const float b0v = sBias[cb], b1v = sBias[cb + 1];
            float v00 = acc[mt][nt][0] + b0v, v01 = acc[mt][nt][1] + b1v;
            float v10 = acc[mt][nt][2] + b0v, v11 = acc[mt][nt][3] + b1v;
            if (OUTMODE == 2) {
                __nv_bfloat162 h0, l0, h1, l1;
                h0.x = __float2bfloat16(v00); h0.y = __float2bfloat16(v01);
                l0.x = __float2bfloat16(v00 - __bfloat162float(h0.x));
                l0.y = __float2bfloat16(v01 - __bfloat162float(h0.y));
                h1.x = __float2bfloat16(v10); h1.y = __float2bfloat16(v11);
                l1.x = __float2bfloat16(v10 - __bfloat162float(h1.x));
                l1.y = __float2bfloat16(v11 - __bfloat162float(h1.y));
                size_t o0 = (size_t)r0 * ldc + n0 + cb;
                size_t o1 = (size_t)r1 * ldc + n0 + cb;
                *(__nv_bfloat162*)(Chi + o0) = h0;
                *(__nv_bfloat162*)(Clo + o0) = l0;
                *(__nv_bfloat162*)(Chi + o1) = h1;
                *(__nv_bfloat162*)(Clo + o1) = l1;
            } else {
                int row0 = (r0 & 63) * Tt + (r0 >> 6);
                int row1 = (r1 & 63) * Tt + (r1 >> 6);
                *(float2*)(C + (size_t)row0 * ldc + coloff + n0 + cb) = make_float2(v00, v01);
                *(float2*)(C + (size_t)row1 * ldc + coloff + n0 + cb) = make_float2(v10, v11);
            }
        }
    }
}

// xg GEMM: output layout [t][col'][b] with col' = n*4 + gate (mma-friendly)
__global__ void __launch_bounds__(256, 2) gemm_xg(
    const __nv_bfloat16* __restrict__ Ahi, const __nv_bfloat16* __restrict__ Alo,
    const __nv_bfloat16* __restrict__ Bfh, const __nv_bfloat16* __restrict__ Bfl,
    const __nv_bfloat16* __restrict__ Bbh, const __nv_bfloat16* __restrict__ Bbl,
    const float* __restrict__ bf1, const float* __restrict__ bf2,
    const float* __restrict__ bb1, const float* __restrict__ bb2,
    float* __restrict__ Cf, float* __restrict__ Cb, int K)
{
    const __nv_bfloat16* Bhi = blockIdx.z ? Bbh : Bfh;
    const __nv_bfloat16* Blo = blockIdx.z ? Bbl : Bfl;
    const float* bias1 = blockIdx.z ? bb1 : bf1;
    const float* bias2 = blockIdx.z ? bb2 : bf2;
    float* C = blockIdx.z ? Cb : Cf;

    GEMM_PROLOG();
    __shared__ float sBias[64];
    if (tid < 64) sBias[tid] = bias1[n0 + tid] + bias2[n0 + tid];
    GEMM_MAINLOOP();

#pragma unroll
    for (int mt = 0; mt < 2; mt++) {
        const int r0 = m0 + wm * 32 + mt * 16 + g;
        const int r1 = r0 + 8;
        const int t0 = r0 >> 6, b0r = r0 & 63;
        const int t1 = r1 >> 6, b1r = r1 & 63;
#pragma unroll
        for (int nt = 0; nt < 4; nt++) {
            const int cb = wn * 32 + nt * 8 + 2 * tig;
            const float b0v = sBias[cb], b1v = sBias[cb + 1];
            int cg0 = n0 + cb, cg1 = cg0 + 1;
            int cp0 = ((cg0 & 255) << 2) | (cg0 >> 8);
            int cp1 = ((cg1 & 255) << 2) | (cg1 >> 8);
            C[(size_t)t0 * (Bb * G4) + (size_t)cp0 * Bb + b0r] = acc[mt][nt][0] + b0v;
            C[(size_t)t0 * (Bb * G4) + (size_t)cp1 * Bb + b0r] = acc[mt][nt][1] + b1v;
            C[(size_t)t1 * (Bb * G4) + (size_t)cp0 * Bb + b1r] = acc[mt][nt][2] + b0v;
            C[(size_t)t1 * (Bb * G4) + (size_t)cp1 * Bb + b1r] = acc[mt][nt][3] + b1v;
        }
    }
}

// ---------------- tensor-core cluster LSTM: 8 warps x N=16 ----------------
#define SH_ROW   264
#define SH_PLANE (16 * SH_ROW)

#define CLUSTER_SYNC() do { \
    asm volatile("barrier.cluster.arrive.aligned;" ::: "memory"); \
    asm volatile("barrier.cluster.wait.aligned;"   ::: "memory"); \
} while (0)
#define CLUSTER_ARRIVE() asm volatile("barrier.cluster.arrive.aligned;" ::: "memory")
#define CLUSTER_WAIT()   asm volatile("barrier.cluster.wait.aligned;"   ::: "memory")

__global__ void __launch_bounds__(256, 1) __cluster_dims__(8, 1, 1)
lstm_mma(const float* __restrict__ xgf, const float* __restrict__ xgb,
         const float* __restrict__ Whhf, const float* __restrict__ Whhb,
         float* __restrict__ outp,
         __nv_bfloat16* __restrict__ Chi, __nv_bfloat16* __restrict__ Clo,
         int mode)
{
    __shared__ __align__(16) uint16_t sH[2 * 2 * SH_PLANE];
    __shared__ __align__(16) uint16_t sStg[2][16 * 32];

    const int tid  = threadIdx.x;
    const int lane = tid & 31, w = tid >> 5;       // 8 warps
    const int g = lane >> 2, tig = lane & 3;
    uint32_t rank;
    asm("mov.u32 %0, %%cluster_ctarank;" : "=r"(rank));
    const int dir  = blockIdx.x >> 5;
    const int bgrp = (blockIdx.x >> 3) & 3;

    const float* xg  = dir ? xgb : xgf;
    const float* Whh = dir ? Whhb : Whhf;

    // ---- persistent W fragments: warp covers 16 cols = 2 n-tiles ----
    uint32_t Whi[2][16][2], Wlo[2][16][2];
#pragma unroll
    for (int nt = 0; nt < 2; nt++) {
        const int colW = 16 * w + 8 * nt + g;
        const int rowW = (colW & 3) * HH + ((int)rank * 32 + (colW >> 2));
#pragma unroll
        for (int kt = 0; kt < 16; kt++) {
            float2 p0 = *(const float2*)(Whh + (size_t)rowW * HH + kt * 16 + 2 * tig);
            float2 p1 = *(const float2*)(Whh + (size_t)rowW * HH + kt * 16 + 2 * tig + 8);
            __nv_bfloat162 h0, h1, l0, l1;
            h0.x = __float2bfloat16(p0.x); h0.y = __float2bfloat16(p0.y);
            h1.x = __float2bfloat16(p1.x); h1.y = __float2bfloat16(p1.y);
            l0.x = __float2bfloat16(p0.x - __bfloat162float(h0.x));
            l0.y = __float2bfloat16(p0.y - __bfloat162float(h0.y));
            l1.x = __float2bfloat16(p1.x - __bfloat162float(h1.x));
            l1.y = __float2bfloat16(p1.y - __bfloat162float(h1.y));
            Whi[nt][kt][0] = *(uint32_t*)&h0; Whi[nt][kt][1] = *(uint32_t*)&h1;
            Wlo[nt][kt][0] = *(uint32_t*)&l0; Wlo[nt][kt][1] = *(uint32_t*)&l1;
        }
    }

    for (int i = tid; i < 2 * 2 * SH_PLANE; i += 256) sH[i] = 0;

    const uint32_t shb = smem_u32(sH);
    const uint32_t lmOff = (uint32_t)(lane & 15) * (SH_ROW * 2) + ((lane & 16) ? 16u : 0u);

    // cell ownership per n-tile: unit = 4w + 2nt + (tig>>1); b = g or g+8
    const int bLoc  = (tig & 1) ? (g + 8) : g;
    const int bGlob = bgrp * 16 + bLoc;

    // x preact cols: col' = rank*128 + 16w + 8nt + 2tig (+1)
    const int bg0 = bgrp * 16 + g, bg1 = bg0 + 8;
    int tcur = dir ? (Tt - 1) : 0;
    float xv[2][4];
#pragma unroll
    for (int nt = 0; nt < 2; nt++) {
        const int xc = (int)rank * 128 + 16 * w + 8 * nt + 2 * tig;
        const float* xp = xg + (size_t)tcur * (Bb * G4);
        xv[nt][0] = xp[(size_t)xc * Bb + bg0];
        xv[nt][1] = xp[(size_t)(xc + 1) * Bb + bg0];
        xv[nt][2] = xp[(size_t)xc * Bb + bg1];
        xv[nt][3] = xp[(size_t)(xc + 1) * Bb + bg1];
    }

    // broadcast mapping: 256 threads, each ships 2 chunks/plane (peer = tid>>5)
    const int gPeer = tid >> 5;            // 0..7
    const int gB    = (tid >> 1) & 15;     // 0..15
    const int gH    = tid & 1;             // chunk half: chunks {2h, 2h+1}
    const uint32_t stgB = smem_u32(sStg);

    CLUSTER_SYNC();

    float cc[2] = {0.f, 0.f};
    for (int step = 0; step < Tt; step++) {
        const int t    = dir ? (Tt - 1 - step) : step;
        const int rbuf = step & 1;
        const int wbuf = rbuf ^ 1;

        float aA[2][4], aB[2][4], aC[2][4];
#pragma unroll
        for (int nt = 0; nt < 2; nt++)
#pragma unroll
            for (int x = 0; x < 4; x++) { aA[nt][x] = xv[nt][x]; aB[nt][x] = 0.f; aC[nt][x] = 0.f; }

        const uint32_t hiB = shb + (uint32_t)((rbuf * 2 + 0) * SH_PLANE) * 2 + lmOff;
        const uint32_t loB = shb + (uint32_t)((rbuf * 2 + 1) * SH_PLANE) * 2 + lmOff;
#pragma unroll
        for (int kt = 0; kt < 16; kt++) {
            uint32_t ahi[4], alo[4];
            LDMX4(ahi, hiB + kt * 32);
            LDMX4(alo, loB + kt * 32);
            MMA16816(aA[0], ahi, Whi[0][kt]);
            MMA16816(aA[1], ahi, Whi[1][kt]);
            MMA16816(aB[0], ahi, Wlo[0][kt]);
            MMA16816(aB[1], ahi, Wlo[1][kt]);
            MMA16816(aC[0], alo, Whi[0][kt]);
            MMA16816(aC[1], alo, Whi[1][kt]);
        }

        float hcell[2];
        __nv_bfloat16 hh[2], hl[2];
#pragma unroll
        for (int nt = 0; nt < 2; nt++) {
            float a0 = aA[nt][0] + aB[nt][0] + aC[nt][0];
            float a1 = aA[nt][1] + aB[nt][1] + aC[nt][1];
            float a2 = aA[nt][2] + aB[nt][2] + aC[nt][2];
            float a3 = aA[nt][3] + aB[nt][3] + aC[nt][3];
            float t0 = __shfl_xor_sync(0xffffffffu, a0, 1);
            float t1 = __shfl_xor_sync(0xffffffffu, a1, 1);
            float t2 = __shfl_xor_sync(0xffffffffu, a2, 1);
            float t3 = __shfl_xor_sync(0xffffffffu, a3, 1);
            float gi, gf, gg, go;
            if ((tig & 1) == 0) { gi = a0; gf = a1; gg = t0; go = t1; }
            else                { gi = t2; gf = t3; gg = a2; go = a3; }
            float si = fast_sigmoid(gi);
            float sf = fast_sigmoid(gf);
            float so = fast_sigmoid(go);
            cc[nt] = sf * cc[nt] + si * fast_tanh(gg);
            float h = so * fast_tanh(cc[nt]);
            hcell[nt] = h;
            hh[nt] = __float2bfloat16(h);
            hl[nt] = __float2bfloat16(h - __bfloat162float(hh[nt]));
            int uL = 4 * w + 2 * nt + (tig >> 1);
            sStg[0][bLoc * 32 + uL] = *(uint16_t*)&hh[nt];
            sStg[1][bLoc * 32 + uL] = *(uint16_t*)&hl[nt];
        }
        __syncthreads();

        // DSMEM broadcast: thread ships 2 chunks per plane to its peer
        {
#pragma unroll
            for (int ch2 = 0; ch2 < 2; ch2++) {
                int gCh = gH * 2 + ch2;
                uint32_t srcHi = stgB + (uint32_t)(gB * 64 + gCh * 16);
                uint32_t srcLo = srcHi + 1024;
                uint32_t r0v, r1v, r2v, r3v, s0v, s1v, s2v, s3v;
                asm volatile("ld.shared.v4.b32 {%0,%1,%2,%3}, [%4];"
                             : "=r"(r0v), "=r"(r1v), "=r"(r2v), "=r"(r3v) : "r"(srcHi));
                asm volatile("ld.shared.v4.b32 {%0,%1,%2,%3}, [%4];"
                             : "=r"(s0v), "=r"(s1v), "=r"(s2v), "=r"(s3v) : "r"(srcLo));
                uint32_t dHi = shb + (uint32_t)((wbuf * 2 + 0) * SH_PLANE + gB * SH_ROW) * 2
                             + (uint32_t)rank * 64 + gCh * 16;
                uint32_t dLo = dHi + (uint32_t)SH_PLANE * 2;
                uint32_t ra;
                asm("mapa.shared::cluster.u32 %0, %1, %2;" : "=r"(ra) : "r"(dHi), "r"(gPeer));
                asm volatile("st.shared::cluster.v4.b32 [%0], {%1,%2,%3,%4};"
                             :: "r"(ra), "r"(r0v), "r"(r1v), "r"(r2v), "r"(r3v));
                asm("mapa.shared::cluster.u32 %0, %1, %2;" : "=r"(ra) : "r"(dLo), "r"(gPeer));
                asm volatile("st.shared::cluster.v4.b32 [%0], {%1,%2,%3,%4};"
                             :: "r"(ra), "r"(s0v), "r"(s1v), "r"(s2v), "r"(s3v));
            }
        }
        CLUSTER_ARRIVE();

        // hidden behind barrier: output store + next-x prefetch
#pragma unroll
        for (int nt = 0; nt < 2; nt++) {
            int nCell = (int)rank * 32 + 4 * w + 2 * nt + (tig >> 1);
            if (mode == 0) {
                size_t o = ((size_t)t * Bb + bGlob) * DG + dir * HH + nCell;
                Chi[o] = hh[nt];
                Clo[o] = hl[nt];
            } else {
                int row = bGlob * Tt + t;
                outp[(size_t)row * 1536 + 1024 + dir * HH + nCell] = hcell[nt];
            }
        }
        if (step + 1 < Tt) {
            int tn = dir ? (Tt - 2 - step) : (step + 1);
            const float* xp = xg + (size_t)tn * (Bb * G4);
#pragma unroll
            for (int nt = 0; nt < 2; nt++) {
                const int xc = (int)rank * 128 + 16 * w + 8 * nt + 2 * tig;
                xv[nt][0] = xp[(size_t)xc * Bb + bg0];
                xv[nt][1] = xp[(size_t)(xc + 1) * Bb + bg0];
                xv[nt][2] = xp[(size_t)xc * Bb + bg1];
                xv[nt][3] = xp[(size_t)(xc + 1) * Bb + bg1];
            }
        }
        CLUSTER_WAIT();
    }
}

// ---------------- launch ----------------
extern "C" void kernel_launch(void* const* d_in, const int* in_sizes, int n_in,
                              void* d_out, int out_size)
{
    const float* r1  = (const float*)d_in[0];
    const float* r2  = (const float*)d_in[1];
    const float* r3  = (const float*)d_in[2];
    const float* r4  = (const float*)d_in[3];
    const float* U_a = (const float*)d_in[4];
    const float* U_v = (const float*)d_in[5];
    const float* W_a = (const float*)d_in[7];
    const float* b_a = (const float*)d_in[8];
    const float* W_v = (const float*)d_in[9];
    const float* b_v = (const float*)d_in[10];
    const float* W_l = (const float*)d_in[11];
    const float* b_l = (const float*)d_in[12];
    const float* Wih0f = (const float*)d_in[13];
    const float* Whh0f = (const float*)d_in[14];
    const float* bih0f = (const float*)d_in[15];
    const float* bhh0f = (const float*)d_in[16];
    const float* Wih0b = (const float*)d_in[17];
    const float* Whh0b = (const float*)d_in[18];
    const float* bih0b = (const float*)d_in[19];
    const float* bhh0b = (const float*)d_in[20];
    const float* Wih1f = (const float*)d_in[21];
    const float* Whh1f = (const float*)d_in[22];
    const float* bih1f = (const float*)d_in[23];
    const float* bhh1f = (const float*)d_in[24];
    const float* Wih1b = (const float*)d_in[25];
    const float* Whh1b = (const float*)d_in[26];
    const float* bih1b = (const float*)d_in[27];
    const float* bhh1b = (const float*)d_in[28];
    float* out = (float*)d_out;

    float *pxf, *pxb;
    cudaGetSymbolAddress((void**)&pxf, g_xgf);
    cudaGetSymbolAddress((void**)&pxb, g_xgb);
    __nv_bfloat16 *pUhi, *pUlo, *pUah, *pUal, *pUvh, *pUvl, *pXhi, *pXlo, *pYhi, *pYlo;
    __nv_bfloat16 *pWah, *pWal, *pWvh, *pWvl, *pWlh, *pWll;
    __nv_bfloat16 *pW0fh, *pW0fl, *pW0bh, *pW0bl, *pW1fh, *pW1fl, *pW1bh, *pW1bl;
    cudaGetSymbolAddress((void**)&pUhi, g_Uhi); cudaGetSymbolAddress((void**)&pUlo, g_Ulo);
    cudaGetSymbolAddress((void**)&pUah, g_Uah); cudaGetSymbolAddress((void**)&pUal, g_Ual);
    cudaGetSymbolAddress((void**)&pUvh, g_Uvh); cudaGetSymbolAddress((void**)&pUvl, g_Uvl);
    cudaGetSymbolAddress((void**)&pXhi, g_Xhi); cudaGetSymbolAddress((void**)&pXlo, g_Xlo);
    cudaGetSymbolAddress((void**)&pYhi, g_Yhi); cudaGetSymbolAddress((void**)&pYlo, g_Ylo);
    cudaGetSymbolAddress((void**)&pWah, g_Wah); cudaGetSymbolAddress((void**)&pWal, g_Wal);
    cudaGetSymbolAddress((void**)&pWvh, g_Wvh); cudaGetSymbolAddress((void**)&pWvl, g_Wvl);
    cudaGetSymbolAddress((void**)&pWlh, g_Wlh); cudaGetSymbolAddress((void**)&pWll, g_Wll);
    cudaGetSymbolAddress((void**)&pW0fh, g_W0fh); cudaGetSymbolAddress((void**)&pW0fl, g_W0fl);
    cudaGetSymbolAddress((void**)&pW0bh, g_W0bh); cudaGetSymbolAddress((void**)&pW0bl, g_W0bl);
    cudaGetSymbolAddress((void**)&pW1fh, g_W1fh); cudaGetSymbolAddress((void**)&pW1fl, g_W1fl);
    cudaGetSymbolAddress((void**)&pW1bh, g_W1bh); cudaGetSymbolAddress((void**)&pW1bl, g_W1bl);

    cudaFuncSetAttribute(gemm_mma<1>, cudaFuncAttributeMaxDynamicSharedMemorySize, GEMM_SMEM);
    cudaFuncSetAttribute(gemm_mma<2>, cudaFuncAttributeMaxDynamicSharedMemorySize, GEMM_SMEM);
    cudaFuncSetAttribute(gemm_xg,     cudaFuncAttributeMaxDynamicSharedMemorySize, GEMM_SMEM);

    cudaStream_t s2;
    cudaEvent_t evFork, evW0, evMid, evW1, evJoin;
    cudaStreamCreateWithFlags(&s2, cudaStreamNonBlocking);
    cudaEventCreateWithFlags(&evFork, cudaEventDisableTiming);
    cudaEventCreateWithFlags(&evW0,   cudaEventDisableTiming);
    cudaEventCreateWithFlags(&evMid,  cudaEventDisableTiming);
    cudaEventCreateWithFlags(&evW1,   cudaEventDisableTiming);
    cudaEventCreateWithFlags(&evJoin, cudaEventDisableTiming);

    cudaEventRecord(evFork, 0);
    cudaStreamWaitEvent(s2, evFork, 0);

    // branch B stage 1 (s2): W_l/W0f/W0b converts
    {
        CJobs wj;
        wj.in[0] = W_l;   wj.hi[0] = pWlh;  wj.lo[0] = pWll;  wj.K[0] = DM; wj.Kpad[0] = DM; wj.total[0] = DG * DM;
        wj.in[1] = Wih0f; wj.hi[1] = pW0fh; wj.lo[1] = pW0fl; wj.K[1] = DG; wj.Kpad[1] = DG; wj.total[1] = G4 * DG;
        wj.in[2] = Wih0b; wj.hi[2] = pW0bh; wj.lo[2] = pW0bl; wj.K[2] = DG; wj.Kpad[2] = DG; wj.total[2] = G4 * DG;
        convert_batch<<<dim3(2048, 3), 256, 0, s2>>>(wj);
        cudaEventRecord(evW0, s2);
    }
    // branch B stage 2 (s2): a/v inputs+weights and layer-1 weights
    {
        CJobs bj;
        bj.in[0] = U_a;   bj.hi[0] = pUah;  bj.lo[0] = pUal;  bj.K[0] = 100; bj.Kpad[0] = 128; bj.total[0] = TB * 128;
        bj.in[1] = U_v;   bj.hi[1] = pUvh;  bj.lo[1] = pUvl;  bj.K[1] = DG;  bj.Kpad[1] = DG;  bj.total[1] = TB * DG;
        bj.in[2] = W_a;   bj.hi[2] = pWah;  bj.lo[2] = pWal;  bj.K[2] = 100; bj.Kpad[2] = 128; bj.total[2] = DG * 128;
        bj.in[3] = W_v;   bj.hi[3] = pWvh;  bj.lo[3] = pWvl;  bj.K[3] = DG;  bj.Kpad[3] = DG;  bj.total[3] = DG * DG;
        bj.in[4] = Wih1f; bj.hi[4] = pW1fh; bj.lo[4] = pW1fl; bj.K[4] = DG;  bj.Kpad[4] = DG;  bj.total[4] = G4 * DG;
        bj.in[5] = Wih1b; bj.hi[5] = pW1bh; bj.lo[5] = pW1bl; bj.K[5] = DG;  bj.Kpad[5] = DG;  bj.total[5] = G4 * DG;
        convert_batch<<<dim3(TB * DG / 256, 6), 256, 0, s2>>>(bj);
        cudaEventRecord(evW1, s2);
    }

    // branch A (origin): LN head
    stats_kernel<<<256, 256>>>(r1, r2, r3, r4);
    build_u_split<<<TB * DM / 4 / 256, 256>>>(r1, r2, r3, r4);

    cudaStreamWaitEvent(0, evW0, 0);
    gemm_mma<2><<<dim3(8, 48), 256, GEMM_SMEM>>>(pUhi, pUlo, pWlh, pWll, b_l,
                                                 nullptr, pXhi, pXlo, 1024, 512, 0);
    gemm_xg<<<dim3(16, 48, 2), 256, GEMM_SMEM>>>(pXhi, pXlo, pW0fh, pW0fl, pW0bh, pW0bl,
                                                 bih0f, bhh0f, bih0b, bhh0b, pxf, pxb, 512);
    cudaEventRecord(evMid, 0);

    // branch B stage 3 (s2): a/v GEMMs during lstm0's 64-SM window
    cudaStreamWaitEvent(s2, evMid, 0);
    gemm_mma<1><<<dim3(8, 48), 256, GEMM_SMEM, s2>>>(pUah, pUal, pWah, pWal, b_a,
                                                     out, nullptr, nullptr, 128, 1536, 0);
    gemm_mma<1><<<dim3(8, 48), 256, GEMM_SMEM, s2>>>(pUvh, pUvl, pWvh, pWvl, b_v,
                                                     out, nullptr, nullptr, 512, 1536, 512);
    cudaEventRecord(evJoin, s2);

    // branch A phase 2: LSTMs
    lstm_mma<<<64, 256>>>(pxf, pxb, Whh0f, Whh0b, nullptr, pYhi, pYlo, 0);

    cudaStreamWaitEvent(0, evW1, 0);
    gemm_xg<<<dim3(16, 48, 2), 256, GEMM_SMEM>>>(pYhi, pYlo, pW1fh, pW1fl, pW1bh, pW1bl,
                                                 bih1f, bhh1f, bih1b, bhh1b, pxf, pxb, 512);
    lstm_mma<<<64, 256>>>(pxf, pxb, Whh1f, Whh1b, out, nullptr, nullptr, 1);

    cudaStreamWaitEvent(0, evJoin, 0);

    cudaEventDestroy(evFork);
    cudaEventDestroy(evW0);
    cudaEventDestroy(evMid);
    cudaEventDestroy(evW1);
    cudaEventDestroy(evJoin);
    cudaStreamDestroy(s2);
}

// round 17
// speedup vs baseline: 1.0183x; 1.0183x over previous
#include <cuda_runtime.h>
#include <cuda_bf16.h>
#include <math.h>
#include <stdint.h>

// ---------------- problem constants ----------------
#define Tt   96
#define Bb   64
#define TB   6144
#define DM   1024
#define DG   512
#define HH   256
#define G4   1024

// ---------------- scratch ----------------
__device__ float g_xgf[TB * G4];      // transposed [t][col'][b], col' = n*4+gate
__device__ float g_xgb[TB * G4];
__device__ float g_alpha[4 * Bb];
__device__ float g_shift[4 * Bb];

__device__ __nv_bfloat16 g_Uhi[TB * DM],  g_Ulo[TB * DM];
__device__ __nv_bfloat16 g_Uah[TB * 128], g_Ual[TB * 128];
__device__ __nv_bfloat16 g_Uvh[TB * DG],  g_Uvl[TB * DG];
__device__ __nv_bfloat16 g_Xhi[TB * DG],  g_Xlo[TB * DG];
__device__ __nv_bfloat16 g_Yhi[TB * DG],  g_Ylo[TB * DG];
__device__ __nv_bfloat16 g_Wah[DG * 128], g_Wal[DG * 128];
__device__ __nv_bfloat16 g_Wvh[DG * DG],  g_Wvl[DG * DG];
__device__ __nv_bfloat16 g_Wlh[DG * DM],  g_Wll[DG * DM];
__device__ __nv_bfloat16 g_W0fh[G4 * DG], g_W0fl[G4 * DG];
__device__ __nv_bfloat16 g_W0bh[G4 * DG], g_W0bl[G4 * DG];
__device__ __nv_bfloat16 g_W1fh[G4 * DG], g_W1fl[G4 * DG];
__device__ __nv_bfloat16 g_W1bh[G4 * DG], g_W1bl[G4 * DG];

// ---------------- helpers ----------------
__device__ __forceinline__ uint32_t smem_u32(const void* p) {
    uint32_t a;
    asm("{ .reg .u64 t; cvta.to.shared.u64 t, %1; cvt.u32.u64 %0, t; }" : "=r"(a) : "l"(p));
    return a;
}
__device__ __forceinline__ float fast_ex2(float x) {
    float r; asm("ex2.approx.f32 %0, %1;" : "=f"(r) : "f"(x)); return r;
}
__device__ __forceinline__ float fast_rcp(float x) {
    float r; asm("rcp.approx.f32 %0, %1;" : "=f"(r) : "f"(x)); return r;
}
__device__ __forceinline__ float fast_sigmoid(float x) {
    return fast_rcp(1.f + fast_ex2(-1.4426950408889634f * x));
}
__device__ __forceinline__ float fast_tanh(float x) {
    return 1.f - 2.f * fast_rcp(1.f + fast_ex2(2.8853900817779268f * x));
}
#define CP16(dst, src) \
    asm volatile("cp.async.cg.shared.global [%0], [%1], 16;" :: "r"(dst), "l"(src))
#define CP_COMMIT() asm volatile("cp.async.commit_group;" ::: "memory")
#define CP_WAIT(n)  asm volatile("cp.async.wait_group %0;" :: "n"(n) : "memory")

#define MMA16816(d, a, b) \
    asm volatile("mma.sync.aligned.m16n8k16.row.col.f32.bf16.bf16.f32 " \
        "{%0,%1,%2,%3}, {%4,%5,%6,%7}, {%8,%9}, {%0,%1,%2,%3};" \
        : "+f"((d)[0]), "+f"((d)[1]), "+f"((d)[2]), "+f"((d)[3]) \
        : "r"((a)[0]), "r"((a)[1]), "r"((a)[2]), "r"((a)[3]), "r"((b)[0]), "r"((b)[1]))

#define LDMX4(r, a) \
    asm volatile("ldmatrix.sync.aligned.m8n8.x4.shared.b16 {%0,%1,%2,%3}, [%4];" \
        : "=r"((r)[0]), "=r"((r)[1]), "=r"((r)[2]), "=r"((r)[3]) : "r"(a))

#define MBARRIER_INIT(addr, cnt) \
    asm volatile("mbarrier.init.shared.b64 [%0], %1;" :: "r"((uint32_t)(addr)), "r"((uint32_t)(cnt)) : "memory")

// cluster-scope parity wait (acquire)
#define MBAR_WAIT_CL(addr, par) do { \
    uint32_t _m = (uint32_t)(addr), _p = (uint32_t)(par), _d; \
    asm volatile("{\n\t.reg .pred p;\n\t" \
        "mbarrier.try_wait.parity.acquire.cluster.shared::cta.b64 p, [%1], %2;\n\t" \
        "selp.b32 %0, 1, 0, p;\n\t}" : "=r"(_d) : "r"(_m), "r"(_p) : "memory"); \
    if (!_d) { \
        asm volatile("{\n\t.reg .pred P1;\n\t" \
            "WL_%=:\n\t" \
            "mbarrier.try_wait.parity.acquire.cluster.shared::cta.b64 P1, [%0], %1, 0x989680;\n\t" \
            "@P1 bra.uni WD_%=;\n\t" \
            "bra.uni WL_%=;\n\t" \
            "WD_%=:\n\t}" :: "r"(_m), "r"(_p) : "memory"); \
    } \
} while (0)

// ---------------- LN2 statistics ----------------
__global__ void stats_kernel(const float* __restrict__ r1, const float* __restrict__ r2,
                             const float* __restrict__ r3, const float* __restrict__ r4)
{
    int i = blockIdx.x >> 6;
    int b = blockIdx.x & 63;
    const float* r = (i == 0) ? r1 : (i == 1) ? r2 : (i == 2) ? r3 : r4;
    float s = 0.f, q = 0.f;
    const float4* base = (const float4*)(r + (size_t)b * DM);
    for (int t = 0; t < Tt; t++) {
        float4 v = base[(size_t)t * (Bb * DM / 4) + threadIdx.x];
        s += v.x + v.y + v.z + v.w;
        q += v.x * v.x + v.y * v.y + v.z * v.z + v.w * v.w;
    }
    __shared__ float ss[256], sq[256];
    ss[threadIdx.x] = s; sq[threadIdx.x] = q;
    __syncthreads();
    for (int st = 128; st > 0; st >>= 1) {
        if (threadIdx.x < st) { ss[threadIdx.x] += ss[threadIdx.x + st]; sq[threadIdx.x] += sq[threadIdx.x + st]; }
        __syncthreads();
    }
    if (threadIdx.x == 0) {
        const float inv_n = 1.f / (float)(Tt * DM);
        float m   = ss[0] * inv_n;
        float var = sq[0] * inv_n - m * m;
        float a   = 0.25f * rsqrtf(var + 1e-5f);
        g_alpha[i * Bb + b] = a;
        g_shift[i * Bb + b] = a * m;
    }
}

// ---------------- fused U build + bf16 split ----------------
__global__ void build_u_split(const float* __restrict__ r1, const float* __restrict__ r2,
                              const float* __restrict__ r3, const float* __restrict__ r4)
{
    size_t idx = (size_t)blockIdx.x * blockDim.x + threadIdx.x;
    size_t e   = idx * 4;
    int b = (int)((e >> 10) & 63);
    float a1 = g_alpha[b], a2 = g_alpha[64 + b], a3 = g_alpha[128 + b], a4 = g_alpha[192 + b];
    float sh = g_shift[b] + g_shift[64 + b] + g_shift[128 + b] + g_shift[192 + b];
    float4 v1 = ((const float4*)r1)[idx];
    float4 v2 = ((const float4*)r2)[idx];
    float4 v3 = ((const float4*)r3)[idx];
    float4 v4 = ((const float4*)r4)[idx];
    float o[4];
    o[0] = a1 * v1.x + a2 * v2.x + a3 * v3.x + a4 * v4.x - sh;
    o[1] = a1 * v1.y + a2 * v2.y + a3 * v3.y + a4 * v4.y - sh;
    o[2] = a1 * v1.z + a2 * v2.z + a3 * v3.z + a4 * v4.z - sh;
    o[3] = a1 * v1.w + a2 * v2.w + a3 * v3.w + a4 * v4.w - sh;
    __nv_bfloat162 hi0, hi1, lo0, lo1;
    hi0.x = __float2bfloat16(o[0]); hi0.y = __float2bfloat16(o[1]);
    hi1.x = __float2bfloat16(o[2]); hi1.y = __float2bfloat16(o[3]);
    lo0.x = __float2bfloat16(o[0] - __bfloat162float(hi0.x));
    lo0.y = __float2bfloat16(o[1] - __bfloat162float(hi0.y));
    lo1.x = __float2bfloat16(o[2] - __bfloat162float(hi1.x));
    lo1.y = __float2bfloat16(o[3] - __bfloat162float(hi1.y));
    ((__nv_bfloat162*)g_Uhi)[idx * 2]     = hi0;
    ((__nv_bfloat162*)g_Uhi)[idx * 2 + 1] = hi1;
    ((__nv_bfloat162*)g_Ulo)[idx * 2]     = lo0;
    ((__nv_bfloat162*)g_Ulo)[idx * 2 + 1] = lo1;
}

// ---------------- batched fp32 -> bf16 hi/lo ----------------
struct CJobs {
    const float*   in[7];
    __nv_bfloat16* hi[7];
    __nv_bfloat16* lo[7];
    int K[7], Kpad[7], total[7];
};
__global__ void convert_batch(CJobs j)
{
    int job = blockIdx.y;
    int idx = blockIdx.x * 256 + threadIdx.x;
    if (idx >= j.total[job]) return;
    int K = j.K[job], Kp = j.Kpad[job];
    int r = idx / Kp, c = idx - r * Kp;
    float v = (c < K) ? j.in[job][(size_t)r * K + c] : 0.f;
    __nv_bfloat16 h = __float2bfloat16(v);
    j.hi[job][idx] = h;
    j.lo[job][idx] = __float2bfloat16(v - __bfloat162float(h));
}

// ---------------- bf16-split GEMM, 128x64 tile, 3-stage, ldmatrix frags ----------------
#define RSTRIDE 80
#define ATSZ    (128 * RSTRIDE)
#define BTSZ    (64 * RSTRIDE)
#define STG_SZ  (2 * ATSZ + 2 * BTSZ)
#define SM_TILES 256
#define GEMM_SMEM (SM_TILES + 3 * STG_SZ)

#define GEMM_PROLOG() \
    extern __shared__ char smem[]; \
    const uint32_t sb = smem_u32(smem); \
    const int tid  = threadIdx.x; \
    const int lane = tid & 31, wid = tid >> 5; \
    const int wm = wid >> 1, wn = wid & 1; \
    const int g = lane >> 2, tig = lane & 3; \
    const int aRow = (lane & 7) + ((lane >> 3) & 1) * 8; \
    const int aCol = ((lane >> 4) & 1) * 16; \
    const int bRow = (lane & 7) + ((lane >> 4) & 1) * 8; \
    const int bCol = ((lane >> 3) & 1) * 16; \
    const int n0 = blockIdx.x * 64, m0 = blockIdx.y * 128; \
    float acc[2][4][4]; \
    _Pragma("unroll") for (int i = 0; i < 2; i++) \
    _Pragma("unroll") for (int jj = 0; jj < 4; jj++) \
    _Pragma("unroll") for (int x = 0; x < 4; x++) acc[i][jj][x] = 0.f;

#define LOAD_STAGE(st, ch) do { \
    int kc = (ch) << 5; \
    uint32_t stg = sb + SM_TILES + (st) * STG_SZ; \
    { int r = (tid * 2) >> 2, q = (tid * 2) & 3; \
      size_t off = (size_t)(m0 + r) * K + kc + q * 8; \
      uint32_t d = stg + r * RSTRIDE + q * 16; \
      CP16(d, Ahi + off); CP16(d + ATSZ, Alo + off); } \
    { int r = (tid * 2 + 1) >> 2, q = (tid * 2 + 1) & 3; \
      size_t off = (size_t)(m0 + r) * K + kc + q * 8; \
      uint32_t d = stg + r * RSTRIDE + q * 16; \
      CP16(d, Ahi + off); CP16(d + ATSZ, Alo + off); } \
    { int r = tid >> 2, q = tid & 3; \
      size_t off = (size_t)(n0 + r) * K + kc + q * 8; \
      uint32_t d = stg + 2 * ATSZ + r * RSTRIDE + q * 16; \
      CP16(d, Bhi + off); CP16(d + BTSZ, Blo + off); } \
    CP_COMMIT(); \
} while (0)

#define COMPUTE_STAGE(st) do { \
    uint32_t stg = sb + SM_TILES + (st) * STG_SZ; \
    uint32_t sAh = stg, sAl = stg + ATSZ, sBh = stg + 2 * ATSZ, sBl = stg + 2 * ATSZ + BTSZ; \
    _Pragma("unroll") \
    for (int kh = 0; kh < 2; kh++) { \
        uint32_t ah[2][4], al[2][4], bhv[2][4], blv[2][4]; \
        _Pragma("unroll") \
        for (int mt = 0; mt < 2; mt++) { \
            uint32_t ra = (uint32_t)(wm * 32 + mt * 16 + aRow) * RSTRIDE + kh * 32 + aCol; \
            LDMX4(ah[mt], sAh + ra); \
            LDMX4(al[mt], sAl + ra); \
        } \
        _Pragma("unroll") \
        for (int np = 0; np < 2; np++) { \
            uint32_t rb = (uint32_t)(wn * 32 + np * 16 + bRow) * RSTRIDE + kh * 32 + bCol; \
            LDMX4(bhv[np], sBh + rb); \
            LDMX4(blv[np], sBl + rb); \
        } \
        _Pragma("unroll") \
        for (int mt = 0; mt < 2; mt++) \
        _Pragma("unroll") \
            for (int nt = 0; nt < 4; nt++) MMA16816(acc[mt][nt], ah[mt], &bhv[nt >> 1][(nt & 1) * 2]); \
        _Pragma("unroll") \
        for (int mt = 0; mt < 2; mt++) \
        _Pragma("unroll") \
            for (int nt = 0; nt < 4; nt++) MMA16816(acc[mt][nt], ah[mt], &blv[nt >> 1][(nt & 1) * 2]); \
        _Pragma("unroll") \
        for (int mt = 0; mt < 2; mt++) \
        _Pragma("unroll") \
            for (int nt = 0; nt < 4; nt++) MMA16816(acc[mt][nt], al[mt], &bhv[nt >> 1][(nt & 1) * 2]); \
    } \
} while (0)

#define GEMM_MAINLOOP() \
    const int nch = K >> 5; \
    LOAD_STAGE(0, 0); \
    LOAD_STAGE(1, 1); \
    for (int ch = 0; ch < nch; ch++) { \
        const int st = ch % 3; \
        if (ch + 2 < nch) { CP_WAIT(1); } else { CP_WAIT(0); } \
        __syncthreads(); \
        if (ch + 2 < nch) LOAD_STAGE((ch + 2) % 3, ch + 2); \
        COMPUTE_STAGE(st); \
        __syncthreads(); \
    }

template <int OUTMODE>
__global__ void __launch_bounds__(256, 2) gemm_mma(
    const __nv_bfloat16* __restrict__ Ahi, const __nv_bfloat16* __restrict__ Alo,
    const __nv_bfloat16* __restrict__ Bhi, const __nv_bfloat16* __restrict__ Blo,
    const float* __restrict__ bias1,
    float* __restrict__ C, __nv_bfloat16* __restrict__ Chi, __nv_bfloat16* __restrict__ Clo,
    int K, int ldc, int coloff)
{
    GEMM_PROLOG();
    __shared__ float sBias[64];
    if (tid < 64) sBias[tid] = bias1[n0 + tid];
    GEMM_MAINLOOP();

#pragma unroll
    for (int mt = 0; mt < 2; mt++) {
        const int r0 = m0 + wm * 32 + mt * 16 + g;
        const int r1 = r0 + 8;
#pragma unroll
        for (int nt = 0; nt < 4; nt++) {
            const int cb = wn * 32 + nt * 8 + 2 * tig;
            const float b0v = sBias[cb], b1v = sBias[cb + 1];
            float v00 = acc[mt][nt][0] + b0v, v01 = acc[mt][nt][1] + b1v;
            float v10 = acc[mt][nt][2] + b0v, v11 = acc[mt][nt][3] + b1v;
            if (OUTMODE == 2) {
                __nv_bfloat162 h0, l0, h1, l1;
                h0.x = __float2bfloat16(v00); h0.y = __float2bfloat16(v01);
                l0.x = __float2bfloat16(v00 - __bfloat162float(h0.x));
                l0.y = __float2bfloat16(v01 - __bfloat162float(h0.y));
                h1.x = __float2bfloat16(v10); h1.y = __float2bfloat16(v11);
                l1.x = __float2bfloat16(v10 - __bfloat162float(h1.x));
                l1.y = __float2bfloat16(v11 - __bfloat162float(h1.y));
                size_t o0 = (size_t)r0 * ldc + n0 + cb;
                size_t o1 = (size_t)r1 * ldc + n0 + cb;
                *(__nv_bfloat162*)(Chi + o0) = h0;
                *(__nv_bfloat162*)(Clo + o0) = l0;
                *(__nv_bfloat162*)(Chi + o1) = h1;
                *(__nv_bfloat162*)(Clo + o1) = l1;
            } else {
                int row0 = (r0 & 63) * Tt + (r0 >> 6);
                int row1 = (r1 & 63) * Tt + (r1 >> 6);
                *(float2*)(C + (size_t)row0 * ldc + coloff + n0 + cb) = make_float2(v00, v01);
                *(float2*)(C + (size_t)row1 * ldc + coloff + n0 + cb) = make_float2(v10, v11);
            }
        }
    }
}

// xg GEMM: output layout [t][col'][b] with col' = n*4 + gate (mma-friendly)
__global__ void __launch_bounds__(256, 2) gemm_xg(
    const __nv_bfloat16* __restrict__ Ahi, const __nv_bfloat16* __restrict__ Alo,
    const __nv_bfloat16* __restrict__ Bfh, const __nv_bfloat16* __restrict__ Bfl,
    const __nv_bfloat16* __restrict__ Bbh, const __nv_bfloat16* __restrict__ Bbl,
    const float* __restrict__ bf1, const float* __restrict__ bf2,
    const float* __restrict__ bb1, const float* __restrict__ bb2,
    float* __restrict__ Cf, float* __restrict__ Cb, int K)
{
    const __nv_bfloat16* Bhi = blockIdx.z ? Bbh : Bfh;
    const __nv_bfloat16* Blo = blockIdx.z ? Bbl : Bfl;
    const float* bias1 = blockIdx.z ? bb1 : bf1;
    const float* bias2 = blockIdx.z ? bb2 : bf2;
    float* C = blockIdx.z ? Cb : Cf;

    GEMM_PROLOG();
    __shared__ float sBias[64];
    if (tid < 64) sBias[tid] = bias1[n0 + tid] + bias2[n0 + tid];
    GEMM_MAINLOOP();

#pragma unroll
    for (int mt = 0; mt < 2; mt++) {
        const int r0 = m0 + wm * 32 + mt * 16 + g;
        const int r1 = r0 + 8;
        const int t0 = r0 >> 6, b0r = r0 & 63;
        const int t1 = r1 >> 6, b1r = r1 & 63;
#pragma unroll
        for (int nt = 0; nt < 4; nt++) {
            const int cb = wn * 32 + nt * 8 + 2 * tig;
            const float b0v = sBias[cb], b1v = sBias[cb + 1];
            int cg0 = n0 + cb, cg1 = cg0 + 1;
            int cp0 = ((cg0 & 255) << 2) | (cg0 >> 8);
            int cp1 = ((cg1 & 255) << 2) | (cg1 >> 8);
            C[(size_t)t0 * (Bb * G4) + (size_t)cp0 * Bb + b0r] = acc[mt][nt][0] + b0v;
            C[(size_t)t0 * (Bb * G4) + (size_t)cp1 * Bb + b0r] = acc[mt][nt][1] + b1v;
            C[(size_t)t1 * (Bb * G4) + (size_t)cp0 * Bb + b1r] = acc[mt][nt][2] + b0v;
            C[(size_t)t1 * (Bb * G4) + (size_t)cp1 * Bb + b1r] = acc[mt][nt][3] + b1v;
        }
    }
}

// ---------------- tensor-core cluster LSTM: 8 warps x N=16, mbarrier sync ----------------
#define SH_ROW   264
#define SH_PLANE (16 * SH_ROW)

#define CLUSTER_SYNC() do { \
    asm volatile("barrier.cluster.arrive.aligned;" ::: "memory"); \
    asm volatile("barrier.cluster.wait.aligned;"   ::: "memory"); \
} while (0)

__global__ void __launch_bounds__(256, 1) __cluster_dims__(8, 1, 1)
lstm_mma(const float* __restrict__ xgf, const float* __restrict__ xgb,
         const float* __restrict__ Whhf, const float* __restrict__ Whhb,
         float* __restrict__ outp,
         __nv_bfloat16* __restrict__ Chi, __nv_bfloat16* __restrict__ Clo,
         int mode)
{
    __shared__ __align__(16) uint16_t sH[2 * 2 * SH_PLANE];
    __shared__ __align__(16) uint16_t sStg[2][16 * 32];
    __shared__ __align__(8)  unsigned long long sMbar;

    const int tid  = threadIdx.x;
    const int lane = tid & 31, w = tid >> 5;       // 8 warps
    const int g = lane >> 2, tig = lane & 3;
    uint32_t rank;
    asm("mov.u32 %0, %%cluster_ctarank;" : "=r"(rank));
    const int dir  = blockIdx.x >> 5;
    const int bgrp = (blockIdx.x >> 3) & 3;

    const float* xg  = dir ? xgb : xgf;
    const float* Whh = dir ? Whhb : Whhf;

    // ---- persistent W fragments: warp covers 16 cols = 2 n-tiles ----
    uint32_t Whi[2][16][2], Wlo[2][16][2];
#pragma unroll
    for (int nt = 0; nt < 2; nt++) {
        const int colW = 16 * w + 8 * nt + g;
        const int rowW = (colW & 3) * HH + ((int)rank * 32 + (colW >> 2));
#pragma unroll
        for (int kt = 0; kt < 16; kt++) {
            float2 p0 = *(const float2*)(Whh + (size_t)rowW * HH + kt * 16 + 2 * tig);
            float2 p1 = *(const float2*)(Whh + (size_t)rowW * HH + kt * 16 + 2 * tig + 8);
            __nv_bfloat162 h0, h1, l0, l1;
            h0.x = __float2bfloat16(p0.x); h0.y = __float2bfloat16(p0.y);
            h1.x = __float2bfloat16(p1.x); h1.y = __float2bfloat16(p1.y);
            l0.x = __float2bfloat16(p0.x - __bfloat162float(h0.x));
            l0.y = __float2bfloat16(p0.y - __bfloat162float(h0.y));
            l1.x = __float2bfloat16(p1.x - __bfloat162float(h1.x));
            l1.y = __float2bfloat16(p1.y - __bfloat162float(h1.y));
            Whi[nt][kt][0] = *(uint32_t*)&h0; Whi[nt][kt][1] = *(uint32_t*)&h1;
            Wlo[nt][kt][0] = *(uint32_t*)&l0; Wlo[nt][kt][1] = *(uint32_t*)&l1;
        }
    }

    for (int i = tid; i < 2 * 2 * SH_PLANE; i += 256) sH[i] = 0;

    const uint32_t shb  = smem_u32(sH);
    const uint32_t mbA  = smem_u32(&sMbar);
    if (tid == 0) MBARRIER_INIT(mbA, 8);     // 8 arrivals per phase (one per cluster CTA)
    const uint32_t lmOff = (uint32_t)(lane & 15) * (SH_ROW * 2) + ((lane & 16) ? 16u : 0u);

    // cell ownership per n-tile: unit = 4w + 2nt + (tig>>1); b = g or g+8
    const int bLoc  = (tig & 1) ? (g + 8) : g;
    const int bGlob = bgrp * 16 + bLoc;

    const int bg0 = bgrp * 16 + g, bg1 = bg0 + 8;
    int tcur = dir ? (Tt - 1) : 0;
    float xv[2][4];
#pragma unroll
    for (int nt = 0; nt < 2; nt++) {
        const int xc = (int)rank * 128 + 16 * w + 8 * nt + 2 * tig;
        const float* xp = xg + (size_t)tcur * (Bb * G4);
        xv[nt][0] = xp[(size_t)xc * Bb + bg0];
        xv[nt][1] = xp[(size_t)(xc + 1) * Bb + bg0];
        xv[nt][2] = xp[(size_t)xc * Bb + bg1];
        xv[nt][3] = xp[(size_t)(xc + 1) * Bb + bg1];
    }

    const int gPeer = tid >> 5;            // 0..7
    const int gB    = (tid >> 1) & 15;     // 0..15
    const int gH    = tid & 1;
    const uint32_t stgB = smem_u32(sStg);

    __syncthreads();
    CLUSTER_SYNC();                         // all mbarriers initialized cluster-wide

    float cc[2] = {0.f, 0.f};
    for (int step = 0; step < Tt; step++) {
        const int t    = dir ? (Tt - 1 - step) : step;
        const int rbuf = step & 1;
        const int wbuf = rbuf ^ 1;

        float aA[2][4], aB[2][4], aC[2][4];
#pragma unroll
        for (int nt = 0; nt < 2; nt++)
#pragma unroll
            for (int x = 0; x < 4; x++) { aA[nt][x] = xv[nt][x]; aB[nt][x] = 0.f; aC[nt][x] = 0.f; }

        const uint32_t hiB = shb + (uint32_t)((rbuf * 2 + 0) * SH_PLANE) * 2 + lmOff;
        const uint32_t loB = shb + (uint32_t)((rbuf * 2 + 1) * SH_PLANE) * 2 + lmOff;
#pragma unroll
        for (int kt = 0; kt < 16; kt++) {
            uint32_t ahi[4], alo[4];
            LDMX4(ahi, hiB + kt * 32);
            LDMX4(alo, loB + kt * 32);
            MMA16816(aA[0], ahi, Whi[0][kt]);
            MMA16816(aA[1], ahi, Whi[1][kt]);
            MMA16816(aB[0], ahi, Wlo[0][kt]);
            MMA16816(aB[1], ahi, Wlo[1][kt]);
            MMA16816(aC[0], alo, Whi[0][kt]);
            MMA16816(aC[1], alo, Whi[1][kt]);
        }

        float hcell[2];
        __nv_bfloat16 hh[2], hl[2];
#pragma unroll
        for (int nt = 0; nt < 2; nt++) {
            float a0 = aA[nt][0] + aB[nt][0] + aC[nt][0];
            float a1 = aA[nt][1] + aB[nt][1] + aC[nt][1];
            float a2 = aA[nt][2] + aB[nt][2] + aC[nt][2];
            float a3 = aA[nt][3] + aB[nt][3] + aC[nt][3];
            // 2-shfl gate exchange: even lanes need partner a0,a1; odd need a2,a3
            float s1 = __shfl_xor_sync(0xffffffffu, (tig & 1) ? a0 : a2, 1);
            float s2 = __shfl_xor_sync(0xffffffffu, (tig & 1) ? a1 : a3, 1);
            float gi, gf, gg, go;
            if ((tig & 1) == 0) { gi = a0; gf = a1; gg = s1; go = s2; }
            else                { gi = s1; gf = s2; gg = a2; go = a3; }
            float si = fast_sigmoid(gi);
            float sf = fast_sigmoid(gf);
            float so = fast_sigmoid(go);
            cc[nt] = sf * cc[nt] + si * fast_tanh(gg);
            float h = so * fast_tanh(cc[nt]);
            hcell[nt] = h;
            hh[nt] = __float2bfloat16(h);
            hl[nt] = __float2bfloat16(h - __bfloat162float(hh[nt]));
            int uL = 4 * w + 2 * nt + (tig >> 1);
            sStg[0][bLoc * 32 + uL] = *(uint16_t*)&hh[nt];
            sStg[1][bLoc * 32 + uL] = *(uint16_t*)&hl[nt];
        }
        __syncthreads();

        // DSMEM broadcast: thread ships 2 chunks per plane to its peer
        {
#pragma unroll
            for (int ch2 = 0; ch2 < 2; ch2++) {
                int gCh = gH * 2 + ch2;
                uint32_t srcHi = stgB + (uint32_t)(gB * 64 + gCh * 16);
                uint32_t srcLo = srcHi + 1024;
                uint32_t r0v, r1v, r2v, r3v, s0v, s1v, s2v, s3v;
                asm volatile("ld.shared.v4.b32 {%0,%1,%2,%3}, [%4];"
                             : "=r"(r0v), "=r"(r1v), "=r"(r2v), "=r"(r3v) : "r"(srcHi));
                asm volatile("ld.shared.v4.b32 {%0,%1,%2,%3}, [%4];"
                             : "=r"(s0v), "=r"(s1v), "=r"(s2v), "=r"(s3v) : "r"(srcLo));
                uint32_t dHi = shb + (uint32_t)((wbuf * 2 + 0) * SH_PLANE + gB * SH_ROW) * 2
                             + (uint32_t)rank * 64 + gCh * 16;
                uint32_t dLo = dHi + (uint32_t)SH_PLANE * 2;
                uint32_t ra;
                asm("mapa.shared::cluster.u32 %0, %1, %2;" : "=r"(ra) : "r"(dHi), "r"(gPeer));
                asm volatile("st.shared::cluster.v4.b32 [%0], {%1,%2,%3,%4};"
                             :: "r"(ra), "r"(r0v), "r"(r1v), "r"(r2v), "r"(r3v));
                asm("mapa.shared::cluster.u32 %0, %1, %2;" : "=r"(ra) : "r"(dLo), "r"(gPeer));
                asm volatile("st.shared::cluster.v4.b32 [%0], {%1,%2,%3,%4};"
                             :: "r"(ra), "r"(s0v), "r"(s1v), "r"(s2v), "r"(s3v));
            }
        }
        __syncthreads();   // all DSMEM stores issued before arrives (happens-before for release)

        // arrive (release, cluster): threads 0..7 each arrive at peer tid's barrier
        if (tid < 8) {
            uint32_t ra;
            asm("mapa.shared::cluster.u32 %0, %1, %2;" : "=r"(ra) : "r"(mbA), "r"(tid));
            asm volatile("mbarrier.arrive.release.cluster.shared::cluster.b64 _, [%0];"
                         :: "r"(ra) : "memory");
        }

        // hidden behind barrier: output store + next-x prefetch
#pragma unroll
        for (int nt = 0; nt < 2; nt++) {
            int nCell = (int)rank * 32 + 4 * w + 2 * nt + (tig >> 1);
            if (mode == 0) {
                size_t o = ((size_t)t * Bb + bGlob) * DG + dir * HH + nCell;
                Chi[o] = hh[nt];
                Clo[o] = hl[nt];
            } else {
                int row = bGlob * Tt + t;
                outp[(size_t)row * 1536 + 1024 + dir * HH + nCell] = hcell[nt];
            }
        }
        if (step + 1 < Tt) {
            int tn = dir ? (Tt - 2 - step) : (step + 1);
            const float* xp = xg + (size_t)tn * (Bb * G4);
#pragma unroll
            for (int nt = 0; nt < 2; nt++) {
                const int xc = (int)rank * 128 + 16 * w + 8 * nt + 2 * tig;
                xv[nt][0] = xp[(size_t)xc * Bb + bg0];
                xv[nt][1] = xp[(size_t)(xc + 1) * Bb + bg0];
                xv[nt][2] = xp[(size_t)xc * Bb + bg1];
                xv[nt][3] = xp[(size_t)(xc + 1) * Bb + bg1];
            }
        }

        // wait for all 8 arrivals (acquire, cluster); parity flips each step
        MBAR_WAIT_CL(mbA, step & 1);
    }
    // final cluster sync: no CTA exits while peers may still target its SMEM
    CLUSTER_SYNC();
}

// ---------------- launch ----------------
extern "C" void kernel_launch(void* const* d_in, const int* in_sizes, int n_in,
                              void* d_out, int out_size)
{
    const float* r1  = (const float*)d_in[0];
    const float* r2  = (const float*)d_in[1];
    const float* r3  = (const float*)d_in[2];
    const float* r4  = (const float*)d_in[3];
    const float* U_a = (const float*)d_in[4];
    const float* U_v = (const float*)d_in[5];
    const float* W_a = (const float*)d_in[7];
    const float* b_a = (const float*)d_in[8];
    const float* W_v = (const float*)d_in[9];
    const float* b_v = (const float*)d_in[10];
    const float* W_l = (const float*)d_in[11];
    const float* b_l = (const float*)d_in[12];
    const float* Wih0f = (const float*)d_in[13];
    const float* Whh0f = (const float*)d_in[14];
    const float* bih0f = (const float*)d_in[15];
    const float* bhh0f = (const float*)d_in[16];
    const float* Wih0b = (const float*)d_in[17];
    const float* Whh0b = (const float*)d_in[18];
    const float* bih0b = (const float*)d_in[19];
    const float* bhh0b = (const float*)d_in[20];
    const float* Wih1f = (const float*)d_in[21];
    const float* Whh1f = (const float*)d_in[22];
    const float* bih1f = (const float*)d_in[23];
    const float* bhh1f = (const float*)d_in[24];
    const float* Wih1b = (const float*)d_in[25];
    const float* Whh1b = (const float*)d_in[26];
    const float* bih1b = (const float*)d_in[27];
    const float* bhh1b = (const float*)d_in[28];
    float* out = (float*)d_out;

    float *pxf, *pxb;
    cudaGetSymbolAddress((void**)&pxf, g_xgf);
    cudaGetSymbolAddress((void**)&pxb, g_xgb);
    __nv_bfloat16 *pUhi, *pUlo, *pUah, *pUal, *pUvh, *pUvl, *pXhi, *pXlo, *pYhi, *pYlo;
    __nv_bfloat16 *pWah, *pWal, *pWvh, *pWvl, *pWlh, *pWll;
    __nv_bfloat16 *pW0fh, *pW0fl, *pW0bh, *pW0bl, *pW1fh, *pW1fl, *pW1bh, *pW1bl;
    cudaGetSymbolAddress((void**)&pUhi, g_Uhi); cudaGetSymbolAddress((void**)&pUlo, g_Ulo);
    cudaGetSymbolAddress((void**)&pUah, g_Uah); cudaGetSymbolAddress((void**)&pUal, g_Ual);
    cudaGetSymbolAddress((void**)&pUvh, g_Uvh); cudaGetSymbolAddress((void**)&pUvl, g_Uvl);
    cudaGetSymbolAddress((void**)&pXhi, g_Xhi); cudaGetSymbolAddress((void**)&pXlo, g_Xlo);
    cudaGetSymbolAddress((void**)&pYhi, g_Yhi); cudaGetSymbolAddress((void**)&pYlo, g_Ylo);
    cudaGetSymbolAddress((void**)&pWah, g_Wah); cudaGetSymbolAddress((void**)&pWal, g_Wal);
    cudaGetSymbolAddress((void**)&pWvh, g_Wvh); cudaGetSymbolAddress((void**)&pWvl, g_Wvl);
    cudaGetSymbolAddress((void**)&pWlh, g_Wlh); cudaGetSymbolAddress((void**)&pWll, g_Wll);
    cudaGetSymbolAddress((void**)&pW0fh, g_W0fh); cudaGetSymbolAddress((void**)&pW0fl, g_W0fl);
    cudaGetSymbolAddress((void**)&pW0bh, g_W0bh); cudaGetSymbolAddress((void**)&pW0bl, g_W0bl);
    cudaGetSymbolAddress((void**)&pW1fh, g_W1fh); cudaGetSymbolAddress((void**)&pW1fl, g_W1fl);
    cudaGetSymbolAddress((void**)&pW1bh, g_W1bh); cudaGetSymbolAddress((void**)&pW1bl, g_W1bl);

    cudaFuncSetAttribute(gemm_mma<1>, cudaFuncAttributeMaxDynamicSharedMemorySize, GEMM_SMEM);
    cudaFuncSetAttribute(gemm_mma<2>, cudaFuncAttributeMaxDynamicSharedMemorySize, GEMM_SMEM);
    cudaFuncSetAttribute(gemm_xg,     cudaFuncAttributeMaxDynamicSharedMemorySize, GEMM_SMEM);

    cudaStream_t s2;
    cudaEvent_t evFork, evW0, evMid, evW1, evJoin;
    cudaStreamCreateWithFlags(&s2, cudaStreamNonBlocking);
    cudaEventCreateWithFlags(&evFork, cudaEventDisableTiming);
    cudaEventCreateWithFlags(&evW0,   cudaEventDisableTiming);
    cudaEventCreateWithFlags(&evMid,  cudaEventDisableTiming);
    cudaEventCreateWithFlags(&evW1,   cudaEventDisableTiming);
    cudaEventCreateWithFlags(&evJoin, cudaEventDisableTiming);

    cudaEventRecord(evFork, 0);
    cudaStreamWaitEvent(s2, evFork, 0);

    // branch B stage 1 (s2): W_l/W0f/W0b converts
    {
        CJobs wj;
        wj.in[0] = W_l;   wj.hi[0] = pWlh;  wj.lo[0] = pWll;  wj.K[0] = DM; wj.Kpad[0] = DM; wj.total[0] = DG * DM;
        wj.in[1] = Wih0f; wj.hi[1] = pW0fh; wj.lo[1] = pW0fl; wj.K[1] = DG; wj.Kpad[1] = DG; wj.total[1] = G4 * DG;
        wj.in[2] = Wih0b; wj.hi[2] = pW0bh; wj.lo[2] = pW0bl; wj.K[2] = DG; wj.Kpad[2] = DG; wj.total[2] = G4 * DG;
        convert_batch<<<dim3(2048, 3), 256, 0, s2>>>(wj);
        cudaEventRecord(evW0, s2);
    }
    // branch B stage 2 (s2): a/v inputs+weights and layer-1 weights
    {
        CJobs bj;
        bj.in[0] = U_a;   bj.hi[0] = pUah;  bj.lo[0] = pUal;  bj.K[0] = 100; bj.Kpad[0] = 128; bj.total[0] = TB * 128;
        bj.in[1] = U_v;   bj.hi[1] = pUvh;  bj.lo[1] = pUvl;  bj.K[1] = DG;  bj.Kpad[1] = DG;  bj.total[1] = TB * DG;
        bj.in[2] = W_a;   bj.hi[2] = pWah;  bj.lo[2] = pWal;  bj.K[2] = 100; bj.Kpad[2] = 128; bj.total[2] = DG * 128;
        bj.in[3] = W_v;   bj.hi[3] = pWvh;  bj.lo[3] = pWvl;  bj.K[3] = DG;  bj.Kpad[3] = DG;  bj.total[3] = DG * DG;
        bj.in[4] = Wih1f; bj.hi[4] = pW1fh; bj.lo[4] = pW1fl; bj.K[4] = DG;  bj.Kpad[4] = DG;  bj.total[4] = G4 * DG;
        bj.in[5] = Wih1b; bj.hi[5] = pW1bh; bj.lo[5] = pW1bl; bj.K[5] = DG;  bj.Kpad[5] = DG;  bj.total[5] = G4 * DG;
        convert_batch<<<dim3(TB * DG / 256, 6), 256, 0, s2>>>(bj);
        cudaEventRecord(evW1, s2);
    }

    // branch A (origin): LN head
    stats_kernel<<<256, 256>>>(r1, r2, r3, r4);
    build_u_split<<<TB * DM / 4 / 256, 256>>>(r1, r2, r3, r4);

    cudaStreamWaitEvent(0, evW0, 0);
    gemm_mma<2><<<dim3(8, 48), 256, GEMM_SMEM>>>(pUhi, pUlo, pWlh, pWll, b_l,
                                                 nullptr, pXhi, pXlo, 1024, 512, 0);
    gemm_xg<<<dim3(16, 48, 2), 256, GEMM_SMEM>>>(pXhi, pXlo, pW0fh, pW0fl, pW0bh, pW0bl,
                                                 bih0f, bhh0f, bih0b, bhh0b, pxf, pxb, 512);
    cudaEventRecord(evMid, 0);

    // branch B stage 3 (s2): a/v GEMMs during lstm0's 64-SM window
    cudaStreamWaitEvent(s2, evMid, 0);
    gemm_mma<1><<<dim3(8, 48), 256, GEMM_SMEM, s2>>>(pUah, pUal, pWah, pWal, b_a,
                                                     out, nullptr, nullptr, 128, 1536, 0);
    gemm_mma<1><<<dim3(8, 48), 256, GEMM_SMEM, s2>>>(pUvh, pUvl, pWvh, pWvl, b_v,
                                                     out, nullptr, nullptr, 512, 1536, 512);
    cudaEventRecord(evJoin, s2);

    // branch A phase 2: LSTMs
    lstm_mma<<<64, 256>>>(pxf, pxb, Whh0f, Whh0b, nullptr, pYhi, pYlo, 0);

    cudaStreamWaitEvent(0, evW1, 0);
    gemm_xg<<<dim3(16, 48, 2), 256, GEMM_SMEM>>>(pYhi, pYlo, pW1fh, pW1fl, pW1bh, pW1bl,
                                                 bih1f, bhh1f, bih1b, bhh1b, pxf, pxb, 512);
    lstm_mma<<<64, 256>>>(pxf, pxb, Whh1f, Whh1b, out, nullptr, nullptr, 1);

    cudaStreamWaitEvent(0, evJoin, 0);

    cudaEventDestroy(evFork);
    cudaEventDestroy(evW0);
    cudaEventDestroy(evMid);
    cudaEventDestroy(evW1);
    cudaEventDestroy(evJoin);
    cudaStreamDestroy(s2);
}